// round 1
// baseline (speedup 1.0000x reference)
#include <cuda_runtime.h>
#include <cstdint>

typedef unsigned long long ull;

#define C_IN   64
#define H_IN   224
#define W_IN   224
#define C_OUT  128
#define H_OUTD 222
#define W_OUTD 222
#define KD     576            // C_IN * 9
#define NPIX   (222 * 222)    // 49284

#define BM 128
#define BN 128
#define BK 8

__device__ __forceinline__ ull pack2(float lo, float hi) {
    ull r;
    asm("mov.b64 %0, {%1, %2};" : "=l"(r) : "f"(lo), "f"(hi));
    return r;
}

__device__ __forceinline__ void fma2(ull &d, ull a, ull b) {
    // packed f32x2 FMA: d.lo += a.lo*b.lo ; d.hi += a.hi*b.hi
    asm("fma.rn.f32x2 %0, %1, %2, %0;" : "+l"(d) : "l"(a), "l"(b));
}

__global__ __launch_bounds__(256, 2)
void conv_impgemm_kernel(const float* __restrict__ x,
                         const float* __restrict__ w,
                         float* __restrict__ out)
{
    __shared__ float As[BK][BM];   // A tile transposed: As[k][co]
    __shared__ float Bs[BK][BN];   // B tile (im2col):   Bs[k][n]

    const int tid = threadIdx.x;
    const int tm  = tid >> 4;          // 0..15  (M micro-tile)
    const int tn  = tid & 15;          // 0..15  (N micro-tile)
    const int n_base = blockIdx.x * BN;

    // A load mapping: thread -> (row=co, 4 consecutive k)
    const int a_row = tid >> 1;        // 0..127
    const int a_kc  = (tid & 1) * 4;   // 0 or 4

    // B load mapping: thread -> (k row, 4 consecutive n)
    const int b_kr = tid >> 5;         // 0..7
    const int b_nc = (tid & 31) * 4;   // 0..124

    ull acc[8][4];                     // acc[i][jp] = cols (2jp, 2jp+1) of row i
#pragma unroll
    for (int i = 0; i < 8; i++)
#pragma unroll
        for (int j = 0; j < 4; j++)
            acc[i][j] = 0ull;

    for (int k0 = 0; k0 < KD; k0 += BK) {
        // ---- load A tile (weights are already [C_OUT, 576] row-major) ----
        const float4 av = *reinterpret_cast<const float4*>(w + a_row * KD + k0 + a_kc);
        As[a_kc + 0][a_row] = av.x;
        As[a_kc + 1][a_row] = av.y;
        As[a_kc + 2][a_row] = av.z;
        As[a_kc + 3][a_row] = av.w;

        // ---- load B tile via on-the-fly im2col ----
        {
            const int k  = k0 + b_kr;
            const int c  = k / 9;
            const int rs = k - c * 9;
            const int r  = rs / 3;
            const int s  = rs - r * 3;
            const float* xp = x + (c * H_IN + r) * W_IN + s;

            const int n0 = n_base + b_nc;
            unsigned ho = (unsigned)n0 / 222u;
            unsigned wo = (unsigned)n0 - ho * 222u;
#pragma unroll
            for (int i = 0; i < 4; i++) {
                float v = 0.0f;
                if (n0 + i < NPIX) v = xp[ho * W_IN + wo];
                Bs[b_kr][b_nc + i] = v;
                wo++;
                if (wo == 222u) { wo = 0u; ho++; }
            }
        }
        __syncthreads();

        // ---- 8x8 register micro-kernel with packed f32x2 FMA ----
#pragma unroll
        for (int kk = 0; kk < BK; kk++) {
            const float4 a0 = *reinterpret_cast<const float4*>(&As[kk][tm * 8]);
            const float4 a1 = *reinterpret_cast<const float4*>(&As[kk][tm * 8 + 4]);
            const ulonglong2 bA = *reinterpret_cast<const ulonglong2*>(&Bs[kk][tn * 8]);
            const ulonglong2 bB = *reinterpret_cast<const ulonglong2*>(&Bs[kk][tn * 8 + 4]);
            const ull bp0 = bA.x, bp1 = bA.y, bp2 = bB.x, bp3 = bB.y;
            const float aa[8] = {a0.x, a0.y, a0.z, a0.w, a1.x, a1.y, a1.z, a1.w};
#pragma unroll
            for (int i = 0; i < 8; i++) {
                const ull ad = pack2(aa[i], aa[i]);   // alu pipe, overlaps fma pipe
                fma2(acc[i][0], ad, bp0);
                fma2(acc[i][1], ad, bp1);
                fma2(acc[i][2], ad, bp2);
                fma2(acc[i][3], ad, bp3);
            }
        }
        __syncthreads();
    }

    // ---- epilogue: float2 stores (NPIX even, n even => pair never straddles) ----
#pragma unroll
    for (int i = 0; i < 8; i++) {
        const int co = tm * 8 + i;
        float* orow = out + (size_t)co * NPIX;
#pragma unroll
        for (int jp = 0; jp < 4; jp++) {
            const int n = n_base + tn * 8 + jp * 2;
            if (n < NPIX) {
                float lo, hi;
                asm("mov.b64 {%0, %1}, %2;" : "=f"(lo), "=f"(hi) : "l"(acc[i][jp]));
                *reinterpret_cast<float2*>(orow + n) = make_float2(lo, hi);
            }
        }
    }
}

extern "C" void kernel_launch(void* const* d_in, const int* in_sizes, int n_in,
                              void* d_out, int out_size)
{
    const float* x = (const float*)d_in[0];       // (64, 224, 224) f32
    const float* w = (const float*)d_in[1];       // (128, 64, 3, 3) f32
    float* out = (float*)d_out;                   // (128, 222, 222) f32

    const int grid = (NPIX + BN - 1) / BN;        // 386 N-tiles, single M-tile
    conv_impgemm_kernel<<<grid, 256>>>(x, w, out);
}

// round 3
// speedup vs baseline: 1.6959x; 1.6959x over previous
#include <cuda_runtime.h>
#include <cuda_bf16.h>
#include <cstdint>

#define H_IN   224
#define W_IN   224
#define NPIX   49284
#define KD     576
#define KC     32
#define NCHUNK 18
#define BN     128

#define A_STRIDE 40    // bf16 per A row (32 k + 8 pad) -> 80B
#define B_STRIDE 136   // bf16 per B row (128 n + 8 pad) -> 272B

__device__ __forceinline__ uint32_t smem_u32(const void* p) {
    uint32_t a;
    asm("{ .reg .u64 t; cvta.to.shared.u64 t, %1; cvt.u32.u64 %0, t; }" : "=r"(a) : "l"(p));
    return a;
}

__device__ __forceinline__ void ldsm_x4(uint32_t (&r)[4], uint32_t addr) {
    asm volatile("ldmatrix.sync.aligned.m8n8.x4.shared.b16 {%0,%1,%2,%3}, [%4];"
                 : "=r"(r[0]), "=r"(r[1]), "=r"(r[2]), "=r"(r[3]) : "r"(addr));
}

__device__ __forceinline__ void ldsm_x2t(uint32_t (&r)[2], uint32_t addr) {
    asm volatile("ldmatrix.sync.aligned.m8n8.x2.trans.shared.b16 {%0,%1}, [%2];"
                 : "=r"(r[0]), "=r"(r[1]) : "r"(addr));
}

__device__ __forceinline__ void mma_bf16(float (&d)[4], const uint32_t (&a)[4],
                                         const uint32_t (&b)[2]) {
    asm volatile(
        "mma.sync.aligned.m16n8k16.row.col.f32.bf16.bf16.f32 "
        "{%0,%1,%2,%3}, {%4,%5,%6,%7}, {%8,%9}, {%0,%1,%2,%3};"
        : "+f"(d[0]), "+f"(d[1]), "+f"(d[2]), "+f"(d[3])
        : "r"(a[0]), "r"(a[1]), "r"(a[2]), "r"(a[3]), "r"(b[0]), "r"(b[1]));
}

__device__ __forceinline__ void split2(float v0, float v1, uint32_t& hi, uint32_t& lo) {
    __nv_bfloat16 h0 = __float2bfloat16_rn(v0), h1 = __float2bfloat16_rn(v1);
    float r0 = v0 - __bfloat162float(h0), r1 = v1 - __bfloat162float(h1);
    __nv_bfloat16 l0 = __float2bfloat16_rn(r0), l1 = __float2bfloat16_rn(r1);
    hi = ((uint32_t)__bfloat16_as_ushort(h1) << 16) | __bfloat16_as_ushort(h0);
    lo = ((uint32_t)__bfloat16_as_ushort(l1) << 16) | __bfloat16_as_ushort(l0);
}

__global__ __launch_bounds__(512, 1)
void conv_mma_kernel(const float* __restrict__ x,
                     const float* __restrict__ w,
                     float* __restrict__ out)
{
    __shared__ __align__(16) __nv_bfloat16 Ah[128 * A_STRIDE];
    __shared__ __align__(16) __nv_bfloat16 Al[128 * A_STRIDE];
    __shared__ __align__(16) __nv_bfloat16 Bh[KC * B_STRIDE];
    __shared__ __align__(16) __nv_bfloat16 Bl[KC * B_STRIDE];

    const int tid  = threadIdx.x;
    const int lane = tid & 31;
    const int wid  = tid >> 5;
    const int wm   = wid >> 2;      // 0..3 -> 32-row band of C_out
    const int wn   = wid & 3;       // 0..3 -> 32-col band of pixels
    const int n_base = blockIdx.x * BN;

    float acc[2][4][4];
#pragma unroll
    for (int i = 0; i < 2; i++)
#pragma unroll
        for (int j = 0; j < 4; j++)
#pragma unroll
            for (int k = 0; k < 4; k++) acc[i][j][k] = 0.0f;

    // ---- staging mappings ----
    const int a_co = tid >> 2;            // 0..127
    const int a_kq = (tid & 3) * 8;       // 0,8,16,24
    const int b_k  = tid >> 4;            // 0..31
    const int b_n0 = (tid & 15) * 8;      // 0..120

    float a_st[8], b_st[8];

    auto stage = [&](int chunk) {
        const int k0 = chunk * KC;
        // A: 8 consecutive k of one co row
        const float4* wp = reinterpret_cast<const float4*>(w + (size_t)a_co * KD + k0 + a_kq);
        float4 v0 = wp[0], v1 = wp[1];
        a_st[0] = v0.x; a_st[1] = v0.y; a_st[2] = v0.z; a_st[3] = v0.w;
        a_st[4] = v1.x; a_st[5] = v1.y; a_st[6] = v1.z; a_st[7] = v1.w;
        // B: im2col, 8 consecutive pixels of one k row
        const int k  = k0 + b_k;
        const int c  = k / 9;
        const int rs = k - c * 9;
        const int r  = rs / 3;
        const int s  = rs - r * 3;
        const float* xp = x + ((size_t)c * H_IN + r) * W_IN + s;
        int n  = n_base + b_n0;
        int ho = n / 222;
        int wo = n - ho * 222;
#pragma unroll
        for (int j = 0; j < 8; j++) {
            b_st[j] = (n + j < NPIX) ? xp[ho * W_IN + wo] : 0.0f;
            wo++;
            if (wo == 222) { wo = 0; ho++; }
        }
    };

    auto commit = [&]() {
        uint32_t hp[4], lp[4];
#pragma unroll
        for (int p = 0; p < 4; p++) split2(a_st[2 * p], a_st[2 * p + 1], hp[p], lp[p]);
        *reinterpret_cast<uint4*>(&Ah[a_co * A_STRIDE + a_kq]) = make_uint4(hp[0], hp[1], hp[2], hp[3]);
        *reinterpret_cast<uint4*>(&Al[a_co * A_STRIDE + a_kq]) = make_uint4(lp[0], lp[1], lp[2], lp[3]);
#pragma unroll
        for (int p = 0; p < 4; p++) split2(b_st[2 * p], b_st[2 * p + 1], hp[p], lp[p]);
        *reinterpret_cast<uint4*>(&Bh[b_k * B_STRIDE + b_n0]) = make_uint4(hp[0], hp[1], hp[2], hp[3]);
        *reinterpret_cast<uint4*>(&Bl[b_k * B_STRIDE + b_n0]) = make_uint4(lp[0], lp[1], lp[2], lp[3]);
    };

    stage(0);
    commit();
    __syncthreads();

    for (int i = 0; i < NCHUNK; i++) {
        if (i + 1 < NCHUNK) stage(i + 1);     // LDGs overlap with compute below

#pragma unroll
        for (int ks = 0; ks < 2; ks++) {
            const int kb = ks * 16;
            uint32_t ah[2][4], al[2][4];
#pragma unroll
            for (int mt = 0; mt < 2; mt++) {
                const int row = wm * 32 + mt * 16 + (lane & 7) + ((lane >> 3) & 1) * 8;
                const int col = kb + ((lane >> 4) << 3);
                ldsm_x4(ah[mt], smem_u32(&Ah[row * A_STRIDE + col]));
                ldsm_x4(al[mt], smem_u32(&Al[row * A_STRIDE + col]));
            }
            uint32_t bh[4][2], bl[4][2];
            const int krow = kb + (lane & 15);
#pragma unroll
            for (int nt = 0; nt < 4; nt++) {
                const int ncol = wn * 32 + nt * 8;
                ldsm_x2t(bh[nt], smem_u32(&Bh[krow * B_STRIDE + ncol]));
                ldsm_x2t(bl[nt], smem_u32(&Bl[krow * B_STRIDE + ncol]));
            }
#pragma unroll
            for (int mt = 0; mt < 2; mt++)
#pragma unroll
                for (int nt = 0; nt < 4; nt++) {
                    mma_bf16(acc[mt][nt], ah[mt], bh[nt]);   // hi*hi
                    mma_bf16(acc[mt][nt], ah[mt], bl[nt]);   // hi*lo
                    mma_bf16(acc[mt][nt], al[mt], bh[nt]);   // lo*hi
                }
        }

        __syncthreads();
        if (i + 1 < NCHUNK) {
            commit();
            __syncthreads();
        }
    }

    // ---- epilogue: frag layout -> float2 stores ----
#pragma unroll
    for (int mt = 0; mt < 2; mt++) {
        const int row0 = wm * 32 + mt * 16 + (lane >> 2);
#pragma unroll
        for (int nt = 0; nt < 4; nt++) {
            const int n = n_base + wn * 32 + nt * 8 + 2 * (lane & 3);
            if (n < NPIX) {
                *reinterpret_cast<float2*>(out + (size_t)row0 * NPIX + n) =
                    make_float2(acc[mt][nt][0], acc[mt][nt][1]);
                *reinterpret_cast<float2*>(out + (size_t)(row0 + 8) * NPIX + n) =
                    make_float2(acc[mt][nt][2], acc[mt][nt][3]);
            }
        }
    }
}

extern "C" void kernel_launch(void* const* d_in, const int* in_sizes, int n_in,
                              void* d_out, int out_size)
{
    const float* x = (const float*)d_in[0];   // (64, 224, 224) f32
    const float* w = (const float*)d_in[1];   // (128, 64, 3, 3) f32
    float* out = (float*)d_out;               // (128, 222, 222) f32

    const int grid = (NPIX + BN - 1) / BN;    // 386
    conv_mma_kernel<<<grid, 512>>>(x, w, out);
}

// round 4
// speedup vs baseline: 2.0511x; 1.2095x over previous
#include <cuda_runtime.h>
#include <cuda_bf16.h>
#include <cstdint>

#define H_IN   224
#define W_IN   224
#define NPIX   49284
#define KD     576
#define KC     32
#define NCHUNK 18
#define BN     128

#define A_STRIDE 40     // bf16 per A row (32 k + 8 pad)
#define B_STRIDE 136    // bf16 per B row (128 n + 8 pad)

#define A_TILE_B (128 * A_STRIDE * 2)   // 10240 B
#define B_TILE_B (KC * B_STRIDE * 2)    // 8704 B
#define OFF_AH(b) ((b) * 2 * A_TILE_B)
#define OFF_AL(b) ((b) * 2 * A_TILE_B + A_TILE_B)
#define AB_TOTAL  (4 * A_TILE_B)
#define OFF_BH(b) (AB_TOTAL + (b) * 2 * B_TILE_B)
#define OFF_BL(b) (AB_TOTAL + (b) * 2 * B_TILE_B + B_TILE_B)
#define SMEM_TOTAL (AB_TOTAL + 4 * B_TILE_B)   // 75776 B

// ---- persistent scratch (static device globals: allowed) ----
__device__ __nv_bfloat16 g_Wh[128 * KD];
__device__ __nv_bfloat16 g_Wl[128 * KD];
__device__ uint32_t      g_X[64 * H_IN * W_IN];   // word = hi | (lo<<16)

__device__ __forceinline__ uint32_t smem_u32(const void* p) {
    uint32_t a;
    asm("{ .reg .u64 t; cvta.to.shared.u64 t, %1; cvt.u32.u64 %0, t; }" : "=r"(a) : "l"(p));
    return a;
}

__device__ __forceinline__ void ldsm_x4(uint32_t (&r)[4], uint32_t addr) {
    asm volatile("ldmatrix.sync.aligned.m8n8.x4.shared.b16 {%0,%1,%2,%3}, [%4];"
                 : "=r"(r[0]), "=r"(r[1]), "=r"(r[2]), "=r"(r[3]) : "r"(addr));
}
__device__ __forceinline__ void ldsm_x2t(uint32_t (&r)[2], uint32_t addr) {
    asm volatile("ldmatrix.sync.aligned.m8n8.x2.trans.shared.b16 {%0,%1}, [%2];"
                 : "=r"(r[0]), "=r"(r[1]) : "r"(addr));
}
__device__ __forceinline__ void mma_bf16(float (&d)[4], const uint32_t (&a)[4],
                                         const uint32_t (&b)[2]) {
    asm volatile(
        "mma.sync.aligned.m16n8k16.row.col.f32.bf16.bf16.f32 "
        "{%0,%1,%2,%3}, {%4,%5,%6,%7}, {%8,%9}, {%0,%1,%2,%3};"
        : "+f"(d[0]), "+f"(d[1]), "+f"(d[2]), "+f"(d[3])
        : "r"(a[0]), "r"(a[1]), "r"(a[2]), "r"(a[3]), "r"(b[0]), "r"(b[1]));
}
__device__ __forceinline__ void cp16(uint32_t dst, const void* src) {
    asm volatile("cp.async.cg.shared.global [%0], [%1], 16;" :: "r"(dst), "l"(src));
}
#define CP_COMMIT() asm volatile("cp.async.commit_group;" ::: "memory")
#define CP_WAIT0()  asm volatile("cp.async.wait_group 0;" ::: "memory")

__device__ __forceinline__ uint32_t pack_split(float v) {
    __nv_bfloat16 h = __float2bfloat16_rn(v);
    __nv_bfloat16 l = __float2bfloat16_rn(v - __bfloat162float(h));
    return (uint32_t)__bfloat16_as_ushort(h) | ((uint32_t)__bfloat16_as_ushort(l) << 16);
}

// ---- pre-kernels: one-time split ----
__global__ void split_w_kernel(const float* __restrict__ w) {
    const int i = blockIdx.x * 256 + threadIdx.x;       // over float4: 18432
    const float4 v = reinterpret_cast<const float4*>(w)[i];
    uint32_t p0 = pack_split(v.x), p1 = pack_split(v.y);
    uint32_t p2 = pack_split(v.z), p3 = pack_split(v.w);
    ushort4 h = make_ushort4((unsigned short)p0, (unsigned short)p1,
                             (unsigned short)p2, (unsigned short)p3);
    ushort4 l = make_ushort4((unsigned short)(p0 >> 16), (unsigned short)(p1 >> 16),
                             (unsigned short)(p2 >> 16), (unsigned short)(p3 >> 16));
    *reinterpret_cast<ushort4*>(&g_Wh[4 * i]) = h;
    *reinterpret_cast<ushort4*>(&g_Wl[4 * i]) = l;
}
__global__ void split_x_kernel(const float* __restrict__ x) {
    const int i = blockIdx.x * 256 + threadIdx.x;       // over float4: 802816
    const float4 v = reinterpret_cast<const float4*>(x)[i];
    uint4 o;
    o.x = pack_split(v.x); o.y = pack_split(v.y);
    o.z = pack_split(v.z); o.w = pack_split(v.w);
    *reinterpret_cast<uint4*>(&g_X[4 * i]) = o;
}

// ---- main implicit-GEMM kernel ----
__global__ __launch_bounds__(512, 1)
void conv_mma_kernel(float* __restrict__ out)
{
    extern __shared__ __align__(16) char smem[];
    const int tid  = threadIdx.x;
    const int lane = tid & 31;
    const int wid  = tid >> 5;
    const int wm   = wid >> 2;
    const int wn   = wid & 3;
    const int n_base = blockIdx.x * BN;

    float acc[2][4][4];
#pragma unroll
    for (int i = 0; i < 2; i++)
#pragma unroll
        for (int j = 0; j < 4; j++)
#pragma unroll
            for (int k = 0; k < 4; k++) acc[i][j][k] = 0.0f;

    // staging maps
    const int a_co = tid >> 2;
    const int a_kq = (tid & 3) * 8;
    const int b_k  = tid >> 4;
    const int b_n0 = (tid & 15) * 8;

    uint32_t b_w[8];

    auto issueA = [&](int chunk, int buf) {
        const int k0 = chunk * KC;
        const uint32_t dst_h = smem_u32(smem + OFF_AH(buf) + (a_co * A_STRIDE + a_kq) * 2);
        const uint32_t dst_l = smem_u32(smem + OFF_AL(buf) + (a_co * A_STRIDE + a_kq) * 2);
        cp16(dst_h, &g_Wh[a_co * KD + k0 + a_kq]);
        cp16(dst_l, &g_Wl[a_co * KD + k0 + a_kq]);
    };

    auto stageB = [&](int chunk) {
        const int k  = chunk * KC + b_k;
        const int c  = k / 9;
        const int rs = k - c * 9;
        const int r  = rs / 3;
        const int s  = rs - r * 3;
        const uint32_t* xp = g_X + ((size_t)c * H_IN + r) * W_IN + s;
        int n  = n_base + b_n0;
        int ho = n / 222;
        int wo = n - ho * 222;
#pragma unroll
        for (int j = 0; j < 8; j++) {
            b_w[j] = (n + j < NPIX) ? xp[ho * W_IN + wo] : 0u;
            wo++;
            if (wo == 222) { wo = 0; ho++; }
        }
    };

    auto commitB = [&](int buf) {
        uint32_t hp[4], lp[4];
#pragma unroll
        for (int p = 0; p < 4; p++) {
            hp[p] = __byte_perm(b_w[2 * p], b_w[2 * p + 1], 0x5410);
            lp[p] = __byte_perm(b_w[2 * p], b_w[2 * p + 1], 0x7632);
        }
        *reinterpret_cast<uint4*>(smem + OFF_BH(buf) + (b_k * B_STRIDE + b_n0) * 2) =
            make_uint4(hp[0], hp[1], hp[2], hp[3]);
        *reinterpret_cast<uint4*>(smem + OFF_BL(buf) + (b_k * B_STRIDE + b_n0) * 2) =
            make_uint4(lp[0], lp[1], lp[2], lp[3]);
    };

    // prologue
    issueA(0, 0);
    CP_COMMIT();
    stageB(0);
    commitB(0);
    CP_WAIT0();
    __syncthreads();

    for (int i = 0; i < NCHUNK; i++) {
        const int cur = i & 1, nxt = (i + 1) & 1;
        if (i + 1 < NCHUNK) {
            issueA(i + 1, nxt);
            CP_COMMIT();
            stageB(i + 1);          // LDG latency overlaps the MMA block below
        }

        const char* pAh = smem + OFF_AH(cur);
        const char* pAl = smem + OFF_AL(cur);
        const char* pBh = smem + OFF_BH(cur);
        const char* pBl = smem + OFF_BL(cur);

#pragma unroll
        for (int ks = 0; ks < 2; ks++) {
            const int kb = ks * 16;
            uint32_t ah[2][4], al[2][4];
#pragma unroll
            for (int mt = 0; mt < 2; mt++) {
                const int row = wm * 32 + mt * 16 + (lane & 7) + ((lane >> 3) & 1) * 8;
                const int col = kb + ((lane >> 4) << 3);
                ldsm_x4(ah[mt], smem_u32(pAh + (row * A_STRIDE + col) * 2));
                ldsm_x4(al[mt], smem_u32(pAl + (row * A_STRIDE + col) * 2));
            }
            uint32_t bh[4][2], bl[4][2];
            const int krow = kb + (lane & 15);
#pragma unroll
            for (int nt = 0; nt < 4; nt++) {
                const int ncol = wn * 32 + nt * 8;
                ldsm_x2t(bh[nt], smem_u32(pBh + (krow * B_STRIDE + ncol) * 2));
                ldsm_x2t(bl[nt], smem_u32(pBl + (krow * B_STRIDE + ncol) * 2));
            }
#pragma unroll
            for (int mt = 0; mt < 2; mt++)
#pragma unroll
                for (int nt = 0; nt < 4; nt++) {
                    mma_bf16(acc[mt][nt], ah[mt], bh[nt]);   // hi*hi
                    mma_bf16(acc[mt][nt], ah[mt], bl[nt]);   // hi*lo
                    mma_bf16(acc[mt][nt], al[mt], bh[nt]);   // lo*hi
                }
        }

        if (i + 1 < NCHUNK) {
            commitB(nxt);           // writes buffer freed by previous sync
            CP_WAIT0();
        }
        __syncthreads();
    }

    // epilogue
#pragma unroll
    for (int mt = 0; mt < 2; mt++) {
        const int row0 = wm * 32 + mt * 16 + (lane >> 2);
#pragma unroll
        for (int nt = 0; nt < 4; nt++) {
            const int n = n_base + wn * 32 + nt * 8 + 2 * (lane & 3);
            if (n < NPIX) {
                *reinterpret_cast<float2*>(out + (size_t)row0 * NPIX + n) =
                    make_float2(acc[mt][nt][0], acc[mt][nt][1]);
                *reinterpret_cast<float2*>(out + (size_t)(row0 + 8) * NPIX + n) =
                    make_float2(acc[mt][nt][2], acc[mt][nt][3]);
            }
        }
    }
}

extern "C" void kernel_launch(void* const* d_in, const int* in_sizes, int n_in,
                              void* d_out, int out_size)
{
    const float* x = (const float*)d_in[0];   // (64, 224, 224) f32
    const float* w = (const float*)d_in[1];   // (128, 64, 3, 3) f32
    float* out = (float*)d_out;               // (128, 222, 222) f32

    split_w_kernel<<<72, 256>>>(w);           // 18432 float4
    split_x_kernel<<<3136, 256>>>(x);         // 802816 float4

    cudaFuncSetAttribute(conv_mma_kernel, cudaFuncAttributeMaxDynamicSharedMemorySize, SMEM_TOTAL);
    const int grid = (NPIX + BN - 1) / BN;    // 386
    conv_mma_kernel<<<grid, 512, SMEM_TOTAL>>>(out);
}

// round 5
// speedup vs baseline: 2.2701x; 1.1068x over previous
#include <cuda_runtime.h>
#include <cuda_bf16.h>
#include <cstdint>

#define H_IN   224
#define W_IN   224
#define NPIX   49284
#define KD     576
#define KC     32
#define NCHUNK 18
#define BN     128

#define A_STRIDE 40     // bf16 per A row (32 k + 8 pad)
#define B_STRIDE 136    // bf16 per B row (128 n + 8 pad)

#define A_TILE_B (128 * A_STRIDE * 2)   // 10240 B
#define B_TILE_B (KC * B_STRIDE * 2)    // 8704 B
#define OFF_AH(b) ((b) * 2 * A_TILE_B)
#define OFF_AL(b) ((b) * 2 * A_TILE_B + A_TILE_B)
#define AB_TOTAL  (4 * A_TILE_B)
#define OFF_BH(b) (AB_TOTAL + (b) * 2 * B_TILE_B)
#define OFF_BL(b) (AB_TOTAL + (b) * 2 * B_TILE_B + B_TILE_B)
#define SMEM_TOTAL (AB_TOTAL + 4 * B_TILE_B)   // 75776 B

// ---- persistent scratch (static device globals: allowed) ----
__device__ __nv_bfloat16 g_Wh[128 * KD];
__device__ __nv_bfloat16 g_Wl[128 * KD];
__device__ uint32_t      g_X[64 * H_IN * W_IN];   // word = hi | (lo<<16)

__device__ __forceinline__ uint32_t smem_u32(const void* p) {
    uint32_t a;
    asm("{ .reg .u64 t; cvta.to.shared.u64 t, %1; cvt.u32.u64 %0, t; }" : "=r"(a) : "l"(p));
    return a;
}

__device__ __forceinline__ void ldsm_x4(uint32_t (&r)[4], uint32_t addr) {
    asm volatile("ldmatrix.sync.aligned.m8n8.x4.shared.b16 {%0,%1,%2,%3}, [%4];"
                 : "=r"(r[0]), "=r"(r[1]), "=r"(r[2]), "=r"(r[3]) : "r"(addr));
}
__device__ __forceinline__ void ldsm_x4t(uint32_t (&r)[4], uint32_t addr) {
    asm volatile("ldmatrix.sync.aligned.m8n8.x4.trans.shared.b16 {%0,%1,%2,%3}, [%4];"
                 : "=r"(r[0]), "=r"(r[1]), "=r"(r[2]), "=r"(r[3]) : "r"(addr));
}
__device__ __forceinline__ void mma_bf16(float (&d)[4], const uint32_t (&a)[4],
                                         uint32_t b0, uint32_t b1) {
    asm volatile(
        "mma.sync.aligned.m16n8k16.row.col.f32.bf16.bf16.f32 "
        "{%0,%1,%2,%3}, {%4,%5,%6,%7}, {%8,%9}, {%0,%1,%2,%3};"
        : "+f"(d[0]), "+f"(d[1]), "+f"(d[2]), "+f"(d[3])
        : "r"(a[0]), "r"(a[1]), "r"(a[2]), "r"(a[3]), "r"(b0), "r"(b1));
}
__device__ __forceinline__ void cp16(uint32_t dst, const void* src) {
    asm volatile("cp.async.cg.shared.global [%0], [%1], 16;" :: "r"(dst), "l"(src));
}
#define CP_COMMIT() asm volatile("cp.async.commit_group;" ::: "memory")
#define CP_WAIT0()  asm volatile("cp.async.wait_group 0;" ::: "memory")

__device__ __forceinline__ uint32_t pack_split(float v) {
    __nv_bfloat16 h = __float2bfloat16_rn(v);
    __nv_bfloat16 l = __float2bfloat16_rn(v - __bfloat162float(h));
    return (uint32_t)__bfloat16_as_ushort(h) | ((uint32_t)__bfloat16_as_ushort(l) << 16);
}

// ---- fused pre-kernel: one-time hi/lo split of w and x ----
#define WBLKS 72            // 18432 float4 of w
#define XBLKS 3136          // 802816 float4 of x
__global__ void split_pre_kernel(const float* __restrict__ w, const float* __restrict__ x) {
    const int b = blockIdx.x;
    if (b < WBLKS) {
        const int i = b * 256 + threadIdx.x;
        const float4 v = reinterpret_cast<const float4*>(w)[i];
        uint32_t p0 = pack_split(v.x), p1 = pack_split(v.y);
        uint32_t p2 = pack_split(v.z), p3 = pack_split(v.w);
        *reinterpret_cast<ushort4*>(&g_Wh[4 * i]) =
            make_ushort4((unsigned short)p0, (unsigned short)p1,
                         (unsigned short)p2, (unsigned short)p3);
        *reinterpret_cast<ushort4*>(&g_Wl[4 * i]) =
            make_ushort4((unsigned short)(p0 >> 16), (unsigned short)(p1 >> 16),
                         (unsigned short)(p2 >> 16), (unsigned short)(p3 >> 16));
    } else {
        const int i = (b - WBLKS) * 256 + threadIdx.x;
        const float4 v = reinterpret_cast<const float4*>(x)[i];
        uint4 o;
        o.x = pack_split(v.x); o.y = pack_split(v.y);
        o.z = pack_split(v.z); o.w = pack_split(v.w);
        *reinterpret_cast<uint4*>(&g_X[4 * i]) = o;
    }
}

// ---- main implicit-GEMM kernel ----
__global__ __launch_bounds__(512, 1)
void conv_mma_kernel(float* __restrict__ out)
{
    extern __shared__ __align__(16) char smem[];
    const int tid  = threadIdx.x;
    const int lane = tid & 31;
    const int wid  = tid >> 5;
    const int wm   = wid >> 2;
    const int wn   = wid & 3;
    const int n_base = blockIdx.x * BN;

    float acc[2][4][4];
#pragma unroll
    for (int i = 0; i < 2; i++)
#pragma unroll
        for (int j = 0; j < 4; j++)
#pragma unroll
            for (int k = 0; k < 4; k++) acc[i][j][k] = 0.0f;

    // staging maps
    const int a_co = tid >> 2;
    const int a_kq = (tid & 3) * 8;
    const int b_k  = tid >> 4;
    const int b_n0 = (tid & 15) * 8;

    uint32_t b_w[8];

    auto issueA = [&](int chunk, int buf) {
        const int k0 = chunk * KC;
        cp16(smem_u32(smem + OFF_AH(buf) + (a_co * A_STRIDE + a_kq) * 2),
             &g_Wh[a_co * KD + k0 + a_kq]);
        cp16(smem_u32(smem + OFF_AL(buf) + (a_co * A_STRIDE + a_kq) * 2),
             &g_Wl[a_co * KD + k0 + a_kq]);
    };

    auto stageB = [&](int chunk) {
        const int k  = chunk * KC + b_k;
        const int c  = k / 9;
        const int rs = k - c * 9;
        const int r  = rs / 3;
        const int s  = rs - r * 3;
        const uint32_t* xp = g_X + ((size_t)c * H_IN + r) * W_IN + s;
        int n  = n_base + b_n0;
        int ho = n / 222;
        int wo = n - ho * 222;
#pragma unroll
        for (int j = 0; j < 8; j++) {
            b_w[j] = (n + j < NPIX) ? xp[ho * W_IN + wo] : 0u;
            wo++;
            if (wo == 222) { wo = 0; ho++; }
        }
    };

    auto commitB = [&](int buf) {
        uint32_t hp[4], lp[4];
#pragma unroll
        for (int p = 0; p < 4; p++) {
            hp[p] = __byte_perm(b_w[2 * p], b_w[2 * p + 1], 0x5410);
            lp[p] = __byte_perm(b_w[2 * p], b_w[2 * p + 1], 0x7632);
        }
        *reinterpret_cast<uint4*>(smem + OFF_BH(buf) + (b_k * B_STRIDE + b_n0) * 2) =
            make_uint4(hp[0], hp[1], hp[2], hp[3]);
        *reinterpret_cast<uint4*>(smem + OFF_BL(buf) + (b_k * B_STRIDE + b_n0) * 2) =
            make_uint4(lp[0], lp[1], lp[2], lp[3]);
    };

    // prologue
    issueA(0, 0);
    CP_COMMIT();
    stageB(0);
    commitB(0);
    CP_WAIT0();
    __syncthreads();

    // B x4.trans lane addressing: g = lane>>3 selects matrix
    const int bt_row = (lane & 7) + ((lane >> 3) & 1) * 8;   // k within 16-group
    const int bt_col = ((lane >> 4) & 1) * 8;                // n offset within pair

    for (int i = 0; i < NCHUNK; i++) {
        const int cur = i & 1, nxt = (i + 1) & 1;
        if (i + 1 < NCHUNK) {
            issueA(i + 1, nxt);
            CP_COMMIT();
            stageB(i + 1);          // LDG latency overlaps the MMA block below
        }

        const char* pAh = smem + OFF_AH(cur);
        const char* pAl = smem + OFF_AL(cur);
        const char* pBh = smem + OFF_BH(cur);
        const char* pBl = smem + OFF_BL(cur);

#pragma unroll
        for (int ks = 0; ks < 2; ks++) {
            const int kb = ks * 16;
            uint32_t ah[2][4], al[2][4];
#pragma unroll
            for (int mt = 0; mt < 2; mt++) {
                const int row = wm * 32 + mt * 16 + (lane & 15);
                const int col = kb + ((lane >> 4) << 3);
                ldsm_x4(ah[mt], smem_u32(pAh + (row * A_STRIDE + col) * 2));
                ldsm_x4(al[mt], smem_u32(pAl + (row * A_STRIDE + col) * 2));
            }
            // B: 2 pairs × (h,l); each x4t covers 16k × 16n
            uint32_t bh[2][4], bl[2][4];
            const int krow = kb + bt_row;
#pragma unroll
            for (int pr = 0; pr < 2; pr++) {
                const int ncol = wn * 32 + pr * 16 + bt_col;
                ldsm_x4t(bh[pr], smem_u32(pBh + (krow * B_STRIDE + ncol) * 2));
                ldsm_x4t(bl[pr], smem_u32(pBl + (krow * B_STRIDE + ncol) * 2));
            }
#pragma unroll
            for (int mt = 0; mt < 2; mt++)
#pragma unroll
                for (int nt = 0; nt < 4; nt++) {
                    const int pr = nt >> 1, hf = (nt & 1) * 2;
                    mma_bf16(acc[mt][nt], ah[mt], bh[pr][hf], bh[pr][hf + 1]);  // hi*hi
                    mma_bf16(acc[mt][nt], ah[mt], bl[pr][hf], bl[pr][hf + 1]);  // hi*lo
                    mma_bf16(acc[mt][nt], al[mt], bh[pr][hf], bh[pr][hf + 1]);  // lo*hi
                }
        }

        if (i + 1 < NCHUNK) {
            commitB(nxt);           // writes buffer freed by previous sync
            CP_WAIT0();
        }
        __syncthreads();
    }

    // epilogue
#pragma unroll
    for (int mt = 0; mt < 2; mt++) {
        const int row0 = wm * 32 + mt * 16 + (lane >> 2);
#pragma unroll
        for (int nt = 0; nt < 4; nt++) {
            const int n = n_base + wn * 32 + nt * 8 + 2 * (lane & 3);
            if (n < NPIX) {
                *reinterpret_cast<float2*>(out + (size_t)row0 * NPIX + n) =
                    make_float2(acc[mt][nt][0], acc[mt][nt][1]);
                *reinterpret_cast<float2*>(out + (size_t)(row0 + 8) * NPIX + n) =
                    make_float2(acc[mt][nt][2], acc[mt][nt][3]);
            }
        }
    }
}

extern "C" void kernel_launch(void* const* d_in, const int* in_sizes, int n_in,
                              void* d_out, int out_size)
{
    const float* x = (const float*)d_in[0];   // (64, 224, 224) f32
    const float* w = (const float*)d_in[1];   // (128, 64, 3, 3) f32
    float* out = (float*)d_out;               // (128, 222, 222) f32

    split_pre_kernel<<<WBLKS + XBLKS, 256>>>(w, x);

    cudaFuncSetAttribute(conv_mma_kernel, cudaFuncAttributeMaxDynamicSharedMemorySize, SMEM_TOTAL);
    const int grid = (NPIX + BN - 1) / BN;    // 386
    conv_mma_kernel<<<grid, 512, SMEM_TOTAL>>>(out);
}

// round 6
// speedup vs baseline: 3.0392x; 1.3388x over previous
#include <cuda_runtime.h>
#include <cuda_fp16.h>
#include <cstdint>

#define H_IN   224
#define W_IN   224
#define NPIX   49284
#define KD     576
#define KC     32
#define NCHUNK 18
#define BN     128

#define A_STRIDE 40     // fp16 per A row (32 k + 8 pad)
#define B_STRIDE 136    // fp16 per B row (128 n + 8 pad)

#define A_TILE_B (128 * A_STRIDE * 2)   // 10240 B
#define B_TILE_B (KC * B_STRIDE * 2)    // 8704 B
#define OFF_AH(b) ((b) * 2 * A_TILE_B)
#define OFF_AL(b) ((b) * 2 * A_TILE_B + A_TILE_B)
#define OFF_B(b)  (4 * A_TILE_B + (b) * B_TILE_B)
#define SMEM_TOTAL (4 * A_TILE_B + 2 * B_TILE_B)   // 58368 B

// ---- persistent scratch ----
__device__ __half g_Wh[128 * KD];   // hi part of weights
__device__ __half g_Wl[128 * KD];   // lo part of weights
__device__ __half g_Xh[64 * H_IN * W_IN];

__device__ __forceinline__ uint32_t smem_u32(const void* p) {
    uint32_t a;
    asm("{ .reg .u64 t; cvta.to.shared.u64 t, %1; cvt.u32.u64 %0, t; }" : "=r"(a) : "l"(p));
    return a;
}
__device__ __forceinline__ void ldsm_x4(uint32_t (&r)[4], uint32_t addr) {
    asm volatile("ldmatrix.sync.aligned.m8n8.x4.shared.b16 {%0,%1,%2,%3}, [%4];"
                 : "=r"(r[0]), "=r"(r[1]), "=r"(r[2]), "=r"(r[3]) : "r"(addr));
}
__device__ __forceinline__ void ldsm_x4t(uint32_t (&r)[4], uint32_t addr) {
    asm volatile("ldmatrix.sync.aligned.m8n8.x4.trans.shared.b16 {%0,%1,%2,%3}, [%4];"
                 : "=r"(r[0]), "=r"(r[1]), "=r"(r[2]), "=r"(r[3]) : "r"(addr));
}
__device__ __forceinline__ void mma_f16(float (&d)[4], const uint32_t (&a)[4],
                                        uint32_t b0, uint32_t b1) {
    asm volatile(
        "mma.sync.aligned.m16n8k16.row.col.f32.f16.f16.f32 "
        "{%0,%1,%2,%3}, {%4,%5,%6,%7}, {%8,%9}, {%0,%1,%2,%3};"
        : "+f"(d[0]), "+f"(d[1]), "+f"(d[2]), "+f"(d[3])
        : "r"(a[0]), "r"(a[1]), "r"(a[2]), "r"(a[3]), "r"(b0), "r"(b1));
}
__device__ __forceinline__ void cp16(uint32_t dst, const void* src) {
    asm volatile("cp.async.cg.shared.global [%0], [%1], 16;" :: "r"(dst), "l"(src));
}
#define CP_COMMIT() asm volatile("cp.async.commit_group;" ::: "memory")
#define CP_WAIT0()  asm volatile("cp.async.wait_group 0;" ::: "memory")

// ---- fused pre-kernel ----
#define WBLKS 72            // 18432 float4 of w
#define XBLKS 3136          // 802816 float4 of x
__global__ void split_pre_kernel(const float* __restrict__ w, const float* __restrict__ x) {
    const int b = blockIdx.x;
    if (b < WBLKS) {
        const int i = b * 256 + threadIdx.x;
        const float4 v = reinterpret_cast<const float4*>(w)[i];
        __half h0 = __float2half_rn(v.x), h1 = __float2half_rn(v.y);
        __half h2 = __float2half_rn(v.z), h3 = __float2half_rn(v.w);
        __half l0 = __float2half_rn(v.x - __half2float(h0));
        __half l1 = __float2half_rn(v.y - __half2float(h1));
        __half l2 = __float2half_rn(v.z - __half2float(h2));
        __half l3 = __float2half_rn(v.w - __half2float(h3));
        *reinterpret_cast<ushort4*>(&g_Wh[4 * i]) =
            make_ushort4(__half_as_ushort(h0), __half_as_ushort(h1),
                         __half_as_ushort(h2), __half_as_ushort(h3));
        *reinterpret_cast<ushort4*>(&g_Wl[4 * i]) =
            make_ushort4(__half_as_ushort(l0), __half_as_ushort(l1),
                         __half_as_ushort(l2), __half_as_ushort(l3));
    } else {
        const int i = (b - WBLKS) * 256 + threadIdx.x;
        const float4 v = reinterpret_cast<const float4*>(x)[i];
        *reinterpret_cast<ushort4*>(&g_Xh[4 * i]) =
            make_ushort4(__half_as_ushort(__float2half_rn(v.x)),
                         __half_as_ushort(__float2half_rn(v.y)),
                         __half_as_ushort(__float2half_rn(v.z)),
                         __half_as_ushort(__float2half_rn(v.w)));
    }
}

// ---- main implicit-GEMM kernel ----
__global__ __launch_bounds__(512, 1)
void conv_mma_kernel(float* __restrict__ out)
{
    extern __shared__ __align__(16) char smem[];
    const int tid  = threadIdx.x;
    const int lane = tid & 31;
    const int wid  = tid >> 5;
    const int wm   = wid >> 2;
    const int wn   = wid & 3;
    const int n_base = blockIdx.x * BN;

    float acc[2][4][4];
#pragma unroll
    for (int i = 0; i < 2; i++)
#pragma unroll
        for (int j = 0; j < 4; j++)
#pragma unroll
            for (int k = 0; k < 4; k++) acc[i][j][k] = 0.0f;

    const int a_co = tid >> 2;
    const int a_kq = (tid & 3) * 8;
    const int b_k  = tid >> 4;
    const int b_n0 = (tid & 15) * 8;

    // ---- chunk-invariant im2col offsets for this thread's 8 pixels ----
    uint32_t xoff[8];
    uint32_t vmask = 0;
    {
        int n  = n_base + b_n0;
        int ho = n / 222, wo = n - ho * 222;
#pragma unroll
        for (int j = 0; j < 8; j++) {
            xoff[j] = (uint32_t)(ho * W_IN + wo);
            if (n + j < NPIX) vmask |= (1u << j);
            wo++;
            if (wo == 222) { wo = 0; ho++; }
        }
    }
    const bool full = (vmask == 0xFFu);

    uint32_t b_w[8];

    auto issueA = [&](int chunk, int buf) {
        const int k0 = chunk * KC;
        cp16(smem_u32(smem + OFF_AH(buf) + (a_co * A_STRIDE + a_kq) * 2),
             &g_Wh[a_co * KD + k0 + a_kq]);
        cp16(smem_u32(smem + OFF_AL(buf) + (a_co * A_STRIDE + a_kq) * 2),
             &g_Wl[a_co * KD + k0 + a_kq]);
    };

    auto stageB = [&](int chunk) {
        const int k  = chunk * KC + b_k;
        const int c  = k / 9;
        const int rs = k - c * 9;
        const int r  = rs / 3;
        const int s  = rs - r * 3;
        const __half* bp = g_Xh + ((size_t)c * H_IN + r) * W_IN + s;
        if (full) {
#pragma unroll
            for (int j = 0; j < 8; j++)
                b_w[j] = *reinterpret_cast<const unsigned short*>(bp + xoff[j]);
        } else {
#pragma unroll
            for (int j = 0; j < 8; j++)
                b_w[j] = (vmask >> j) & 1
                       ? (uint32_t)*reinterpret_cast<const unsigned short*>(bp + xoff[j]) : 0u;
        }
    };

    auto commitB = [&](int buf) {
        uint4 o;
        o.x = b_w[0] | (b_w[1] << 16);
        o.y = b_w[2] | (b_w[3] << 16);
        o.z = b_w[4] | (b_w[5] << 16);
        o.w = b_w[6] | (b_w[7] << 16);
        *reinterpret_cast<uint4*>(smem + OFF_B(buf) + (b_k * B_STRIDE + b_n0) * 2) = o;
    };

    // prologue
    issueA(0, 0);
    CP_COMMIT();
    stageB(0);
    commitB(0);
    CP_WAIT0();
    __syncthreads();

    const int bt_row = (lane & 7) + ((lane >> 3) & 1) * 8;
    const int bt_col = ((lane >> 4) & 1) * 8;

    for (int i = 0; i < NCHUNK; i++) {
        const int cur = i & 1, nxt = (i + 1) & 1;
        if (i + 1 < NCHUNK) {
            issueA(i + 1, nxt);
            CP_COMMIT();
            stageB(i + 1);
        }

        const char* pAh = smem + OFF_AH(cur);
        const char* pAl = smem + OFF_AL(cur);
        const char* pB  = smem + OFF_B(cur);

#pragma unroll
        for (int ks = 0; ks < 2; ks++) {
            const int kb = ks * 16;
            uint32_t ah[2][4], al[2][4];
#pragma unroll
            for (int mt = 0; mt < 2; mt++) {
                const int row = wm * 32 + mt * 16 + (lane & 15);
                const int col = kb + ((lane >> 4) << 3);
                ldsm_x4(ah[mt], smem_u32(pAh + (row * A_STRIDE + col) * 2));
                ldsm_x4(al[mt], smem_u32(pAl + (row * A_STRIDE + col) * 2));
            }
            uint32_t bf[2][4];
            const int krow = kb + bt_row;
#pragma unroll
            for (int pr = 0; pr < 2; pr++) {
                const int ncol = wn * 32 + pr * 16 + bt_col;
                ldsm_x4t(bf[pr], smem_u32(pB + (krow * B_STRIDE + ncol) * 2));
            }
#pragma unroll
            for (int mt = 0; mt < 2; mt++)
#pragma unroll
                for (int nt = 0; nt < 4; nt++) {
                    const int pr = nt >> 1, hf = (nt & 1) * 2;
                    mma_f16(acc[mt][nt], ah[mt], bf[pr][hf], bf[pr][hf + 1]);  // Ah*B
                    mma_f16(acc[mt][nt], al[mt], bf[pr][hf], bf[pr][hf + 1]);  // Al*B
                }
        }

        if (i + 1 < NCHUNK) {
            commitB(nxt);
            CP_WAIT0();
        }
        __syncthreads();
    }

    // epilogue
#pragma unroll
    for (int mt = 0; mt < 2; mt++) {
        const int row0 = wm * 32 + mt * 16 + (lane >> 2);
#pragma unroll
        for (int nt = 0; nt < 4; nt++) {
            const int n = n_base + wn * 32 + nt * 8 + 2 * (lane & 3);
            if (n < NPIX) {
                *reinterpret_cast<float2*>(out + (size_t)row0 * NPIX + n) =
                    make_float2(acc[mt][nt][0], acc[mt][nt][1]);
                *reinterpret_cast<float2*>(out + (size_t)(row0 + 8) * NPIX + n) =
                    make_float2(acc[mt][nt][2], acc[mt][nt][3]);
            }
        }
    }
}

extern "C" void kernel_launch(void* const* d_in, const int* in_sizes, int n_in,
                              void* d_out, int out_size)
{
    const float* x = (const float*)d_in[0];   // (64, 224, 224) f32
    const float* w = (const float*)d_in[1];   // (128, 64, 3, 3) f32
    float* out = (float*)d_out;               // (128, 222, 222) f32

    split_pre_kernel<<<WBLKS + XBLKS, 256>>>(w, x);

    cudaFuncSetAttribute(conv_mma_kernel, cudaFuncAttributeMaxDynamicSharedMemorySize, SMEM_TOTAL);
    const int grid = (NPIX + BN - 1) / BN;    // 386
    conv_mma_kernel<<<grid, 512, SMEM_TOTAL>>>(out);
}